// round 8
// baseline (speedup 1.0000x reference)
#include <cuda_runtime.h>
#include <math_constants.h>
#include <cstdint>

// ---------------------------------------------------------------------------
// Net_40312563041045: 4-layer max-tempered MLP
//   h = 0.8 * (X @ W^T) + 0.2 * max_k(W[o,k] * x[b,k]) + b
// B=1024, 256 -> 512 -> 512 -> 512 -> 1, fp32.
//
// R8: linear term on LEGACY tensor cores (mma.sync m16n8k8 tf32, baseline
// PTX — tcgen05 is unavailable because harness emits compute_100 PTX).
// 3xTF32 hi/lo split for fp32 accuracy. Block-role fused kernel per layer:
//   blocks [0,128): max role  — 64x64 tile, MUL2 + FMNMX only (no FADD chain)
//   blocks [128,192): gemm role — 128x64 tile, 8 warps x (32x32), 3 passes
// Combine + tf32-resplit between layers.
// ---------------------------------------------------------------------------

#define BETA 0.2f
#define MAXK_BLOCKS 128
#define NEG_INF __int_as_float(0xff800000)

// ---------------- global scratch (no cudaMalloc allowed) -------------------
__device__ float g_Whi[512 * 512];
__device__ float g_Wlo[512 * 512];
__device__ float g_Ahi[1024 * 512];
__device__ float g_Alo[1024 * 512];
__device__ float g_Hlin[1024 * 512];
__device__ float g_Hmax[1024 * 512];
__device__ float g_act[1024 * 512];

// ---------------- helpers ---------------------------------------------------
__device__ __forceinline__ unsigned smem_u32(const void* p) {
    return (unsigned)__cvta_generic_to_shared(p);
}
__device__ __forceinline__ void cp16(unsigned dst, const void* src) {
    asm volatile("cp.async.ca.shared.global [%0], [%1], 16;\n" :: "r"(dst), "l"(src));
}
__device__ __forceinline__ uint32_t to_tf32(float v) {
    uint32_t t;
    asm("cvt.rna.tf32.f32 %0, %1;" : "=r"(t) : "f"(v));
    return t;
}
__device__ __forceinline__ void mma_tf32(float c[4], const uint32_t a[4],
                                         const uint32_t b[2]) {
    asm volatile(
        "mma.sync.aligned.m16n8k8.row.col.f32.tf32.tf32.f32 "
        "{%0,%1,%2,%3}, {%4,%5,%6,%7}, {%8,%9}, {%0,%1,%2,%3};"
        : "+f"(c[0]), "+f"(c[1]), "+f"(c[2]), "+f"(c[3])
        : "r"(a[0]), "r"(a[1]), "r"(a[2]), "r"(a[3]), "r"(b[0]), "r"(b[1]));
}

// ---------------- split / combine -------------------------------------------
__global__ void __launch_bounds__(256)
split_kernel(const float* __restrict__ src, float* __restrict__ hi,
             float* __restrict__ lo, int n4)
{
    int i = blockIdx.x * blockDim.x + threadIdx.x;
    if (i >= n4) return;
    float4 v = ((const float4*)src)[i];
    float4 h, l;
    h.x = __uint_as_float(to_tf32(v.x)); l.x = __uint_as_float(to_tf32(v.x - h.x));
    h.y = __uint_as_float(to_tf32(v.y)); l.y = __uint_as_float(to_tf32(v.y - h.y));
    h.z = __uint_as_float(to_tf32(v.z)); l.z = __uint_as_float(to_tf32(v.z - h.z));
    h.w = __uint_as_float(to_tf32(v.w)); l.w = __uint_as_float(to_tf32(v.w - h.w));
    ((float4*)hi)[i] = h;
    ((float4*)lo)[i] = l;
}

__global__ void __launch_bounds__(256)
combine_split_kernel(const float* __restrict__ hlin, const float* __restrict__ hmax,
                     float* __restrict__ act, float* __restrict__ hi,
                     float* __restrict__ lo, int n4)
{
    int i = blockIdx.x * blockDim.x + threadIdx.x;
    if (i >= n4) return;
    float4 a = ((const float4*)hlin)[i];
    float4 b = ((const float4*)hmax)[i];
    float4 v, h, l;
    v.x = a.x + b.x; v.y = a.y + b.y; v.z = a.z + b.z; v.w = a.w + b.w;
    h.x = __uint_as_float(to_tf32(v.x)); l.x = __uint_as_float(to_tf32(v.x - h.x));
    h.y = __uint_as_float(to_tf32(v.y)); l.y = __uint_as_float(to_tf32(v.y - h.y));
    h.z = __uint_as_float(to_tf32(v.z)); l.z = __uint_as_float(to_tf32(v.z - h.z));
    h.w = __uint_as_float(to_tf32(v.w)); l.w = __uint_as_float(to_tf32(v.w - h.w));
    ((float4*)act)[i] = v;
    ((float4*)hi)[i]  = h;
    ((float4*)lo)[i]  = l;
}

// ---------------- fused layer kernel ----------------------------------------
// Dynamic smem (floats):
//   gemm role: XHI[128][36]@0, XLO@4608, WHI[64][36]@9216, WLO@11520 (13824 fl)
//   max role:  Xs[2][64][36]@0, Ws[2][64][36]@4608..  (9216 fl)
#define SMEM_BYTES 55296
#define XLO_F 4608
#define WHI_F 9216
#define WLO_F 11520

template <int K>
__global__ void __launch_bounds__(256, 2)
layer_fused(const float* __restrict__ Xf,
            const float* __restrict__ Xhi, const float* __restrict__ Xlo,
            const float* __restrict__ Wf,
            const float* __restrict__ Whi, const float* __restrict__ Wlo,
            const float* __restrict__ bias,
            float* __restrict__ Hlin, float* __restrict__ Hmax, int O)
{
    extern __shared__ float smf[];
    const unsigned sb = smem_u32(smf);
    const int tid = threadIdx.x;

    if (blockIdx.x < MAXK_BLOCKS) {
        // ================= MAX role: 64x64, MUL2 + FMNMX only ===============
        float* Xs = smf;            // [2][64][36]
        float* Ws = smf + 4608;     // [2][64][36]
        const int mb = blockIdx.x;
        const int m0 = (mb & 15) * 64;
        const int n0 = (mb >> 4) * 64;
        const int tcol = tid & 15;
        const int trow = tid >> 4;
        const int srow = tid >> 3;
        const int sc = (tid & 7) * 4;

        float mx[4][4];
#pragma unroll
        for (int i = 0; i < 4; i++)
#pragma unroll
            for (int j = 0; j < 4; j++) mx[i][j] = NEG_INF;

        const float* xg0 = Xf + (size_t)(m0 + srow) * K + sc;
        const float* wg0 = Wf + (size_t)(n0 + srow) * K + sc;
        const int NCH = K / 32;

        cp16(sb + (unsigned)(srow * 36 + sc) * 4, xg0);
        cp16(sb + (unsigned)((srow + 32) * 36 + sc) * 4, xg0 + (size_t)32 * K);
        cp16(sb + 18432u + (unsigned)(srow * 36 + sc) * 4, wg0);
        cp16(sb + 18432u + (unsigned)((srow + 32) * 36 + sc) * 4, wg0 + (size_t)32 * K);
        asm volatile("cp.async.commit_group;\n");

        for (int c = 0; c < NCH; ++c) {
            const int buf = c & 1;
            if (c + 1 < NCH) {
                const int nb = buf ^ 1;
                const int k0 = (c + 1) * 32;
                cp16(sb + (unsigned)(nb * 2304 + srow * 36 + sc) * 4, xg0 + k0);
                cp16(sb + (unsigned)(nb * 2304 + (srow + 32) * 36 + sc) * 4,
                     xg0 + k0 + (size_t)32 * K);
                cp16(sb + 18432u + (unsigned)(nb * 2304 + srow * 36 + sc) * 4, wg0 + k0);
                cp16(sb + 18432u + (unsigned)(nb * 2304 + (srow + 32) * 36 + sc) * 4,
                     wg0 + k0 + (size_t)32 * K);
                asm volatile("cp.async.commit_group;\n");
                asm volatile("cp.async.wait_group 1;\n");
            } else {
                asm volatile("cp.async.wait_group 0;\n");
            }
            __syncthreads();

#pragma unroll
            for (int kk = 0; kk < 32; kk += 4) {
                ulonglong2 xp[4], wp[4];
#pragma unroll
                for (int i = 0; i < 4; i++)
                    xp[i] = *(const ulonglong2*)&Xs[buf * 2304 + (trow * 4 + i) * 36 + kk];
#pragma unroll
                for (int j = 0; j < 4; j++)
                    wp[j] = *(const ulonglong2*)&Ws[buf * 2304 + (tcol + 16 * j) * 36 + kk];
#pragma unroll
                for (int i = 0; i < 4; i++)
#pragma unroll
                    for (int j = 0; j < 4; j++) {
                        asm("{\n\t.reg .b64 p;\n\t.reg .f32 plo, phi;\n\t"
                            "mul.rn.f32x2 p, %1, %2;\n\t"
                            "mov.b64 {plo, phi}, p;\n\t"
                            "max.f32 %0, %0, plo;\n\t"
                            "max.f32 %0, %0, phi;\n\t}"
                            : "+f"(mx[i][j]) : "l"(xp[i].x), "l"(wp[j].x));
                        asm("{\n\t.reg .b64 p;\n\t.reg .f32 plo, phi;\n\t"
                            "mul.rn.f32x2 p, %1, %2;\n\t"
                            "mov.b64 {plo, phi}, p;\n\t"
                            "max.f32 %0, %0, plo;\n\t"
                            "max.f32 %0, %0, phi;\n\t}"
                            : "+f"(mx[i][j]) : "l"(xp[i].y), "l"(wp[j].y));
                    }
            }
            __syncthreads();
        }

#pragma unroll
        for (int i = 0; i < 4; i++) {
            const int m = m0 + trow * 4 + i;
#pragma unroll
            for (int j = 0; j < 4; j++) {
                const int n = n0 + tcol + 16 * j;
                Hmax[(size_t)m * O + n] = BETA * mx[i][j];
            }
        }
    } else {
        // ================= GEMM role: mma.sync tf32, 3x split ===============
        const int gb = blockIdx.x - MAXK_BLOCKS;
        const int m0 = (gb & 7) * 128;
        const int n0 = (gb >> 3) * 64;
        const int w  = tid >> 5;
        const int lane = tid & 31;
        const int wm = w & 3;        // 4 warps over M (32 rows each)
        const int wn = w >> 2;       // 2 warps over N (32 cols each)
        const int lw = lane & 3;     // k-offset within fragment
        const int lr = lane >> 2;    // row/col-offset within fragment

        const uint32_t* XHs = (const uint32_t*)smf;
        const uint32_t* XLs = (const uint32_t*)(smf + XLO_F);
        const uint32_t* WHs = (const uint32_t*)(smf + WHI_F);
        const uint32_t* WLs = (const uint32_t*)(smf + WLO_F);

        float acc[2][4][4];
#pragma unroll
        for (int mt = 0; mt < 2; mt++)
#pragma unroll
            for (int nt = 0; nt < 4; nt++)
#pragma unroll
                for (int e = 0; e < 4; e++) acc[mt][nt][e] = 0.0f;

        const int NCH = K / 32;
        for (int c = 0; c < NCH; ++c) {
            const int k0 = c * 32;
            // stage X hi/lo: 128 rows x 8 chunks each
            for (int idx = tid; idx < 1024; idx += 256) {
                const int r = idx >> 3, q = (idx & 7) * 4;
                const unsigned doff = (unsigned)(r * 36 + q) * 4;
                const size_t g = (size_t)(m0 + r) * K + k0 + q;
                cp16(sb + doff, Xhi + g);
                cp16(sb + XLO_F * 4 + doff, Xlo + g);
            }
            // stage W hi/lo: 64 rows x 8 chunks each
            for (int idx = tid; idx < 512; idx += 256) {
                const int r = idx >> 3, q = (idx & 7) * 4;
                const unsigned doff = (unsigned)(r * 36 + q) * 4;
                const size_t g = (size_t)(n0 + r) * K + k0 + q;
                cp16(sb + WHI_F * 4 + doff, Whi + g);
                cp16(sb + WLO_F * 4 + doff, Wlo + g);
            }
            asm volatile("cp.async.commit_group;\n");
            asm volatile("cp.async.wait_group 0;\n");
            __syncthreads();

#pragma unroll
            for (int kc = 0; kc < 32; kc += 8) {
                uint32_t ah[2][4], al[2][4];
#pragma unroll
                for (int mt = 0; mt < 2; mt++) {
                    const int base = (wm * 32 + mt * 16 + lr) * 36 + kc + lw;
                    ah[mt][0] = XHs[base];
                    ah[mt][1] = XHs[base + 8 * 36];
                    ah[mt][2] = XHs[base + 4];
                    ah[mt][3] = XHs[base + 8 * 36 + 4];
                    al[mt][0] = XLs[base];
                    al[mt][1] = XLs[base + 8 * 36];
                    al[mt][2] = XLs[base + 4];
                    al[mt][3] = XLs[base + 8 * 36 + 4];
                }
                uint32_t bh[4][2], bl[4][2];
#pragma unroll
                for (int nt = 0; nt < 4; nt++) {
                    const int base = (wn * 32 + nt * 8 + lr) * 36 + kc + lw;
                    bh[nt][0] = WHs[base];
                    bh[nt][1] = WHs[base + 4];
                    bl[nt][0] = WLs[base];
                    bl[nt][1] = WLs[base + 4];
                }
#pragma unroll
                for (int mt = 0; mt < 2; mt++)
#pragma unroll
                    for (int nt = 0; nt < 4; nt++) {
                        mma_tf32(acc[mt][nt], ah[mt], bh[nt]);
                        mma_tf32(acc[mt][nt], ah[mt], bl[nt]);
                        mma_tf32(acc[mt][nt], al[mt], bh[nt]);
                    }
            }
            __syncthreads();
        }

        // epilogue: Hlin = 0.8*acc + bias
#pragma unroll
        for (int mt = 0; mt < 2; mt++) {
            const int r0 = m0 + wm * 32 + mt * 16 + lr;
#pragma unroll
            for (int nt = 0; nt < 4; nt++) {
                const int nc = n0 + wn * 32 + nt * 8 + lw * 2;
                const float bia0 = bias[nc], bia1 = bias[nc + 1];
                Hlin[(size_t)r0 * O + nc]           = 0.8f * acc[mt][nt][0] + bia0;
                Hlin[(size_t)r0 * O + nc + 1]       = 0.8f * acc[mt][nt][1] + bia1;
                Hlin[(size_t)(r0 + 8) * O + nc]     = 0.8f * acc[mt][nt][2] + bia0;
                Hlin[(size_t)(r0 + 8) * O + nc + 1] = 0.8f * acc[mt][nt][3] + bia1;
            }
        }
    }
}

// ---------------- final layer -----------------------------------------------
__global__ void __launch_bounds__(256)
layer4_kernel(const float* __restrict__ X, const float* __restrict__ W,
              const float* __restrict__ bias, float* __restrict__ out, int B)
{
    const int row = blockIdx.x * 8 + (threadIdx.x >> 5);
    const int lane = threadIdx.x & 31;
    if (row >= B) return;

    const float4* xr = (const float4*)(X + (size_t)row * 512);
    const float4* wr = (const float4*)W;

    float acc = 0.0f;
    float mx = -CUDART_INF_F;
#pragma unroll
    for (int it = 0; it < 4; ++it) {
        float4 x = xr[lane + 32 * it];
        float4 w = wr[lane + 32 * it];
        float p0 = x.x * w.x, p1 = x.y * w.y, p2 = x.z * w.z, p3 = x.w * w.w;
        acc += (p0 + p1) + (p2 + p3);
        mx = fmaxf(fmaxf(mx, fmaxf(p0, p1)), fmaxf(p2, p3));
    }
#pragma unroll
    for (int o = 16; o > 0; o >>= 1) {
        acc += __shfl_xor_sync(0xffffffff, acc, o);
        mx = fmaxf(mx, __shfl_xor_sync(0xffffffff, mx, o));
    }
    if (lane == 0)
        out[row] = (1.0f - BETA) * acc + BETA * mx + bias[0];
}

// ---------------- launch -----------------------------------------------------
extern "C" void kernel_launch(void* const* d_in, const int* in_sizes, int n_in,
                              void* d_out, int out_size)
{
    const float* x  = (const float*)d_in[0];
    const float* W1 = (const float*)d_in[1];
    const float* b1 = (const float*)d_in[2];
    const float* W2 = (const float*)d_in[3];
    const float* b2 = (const float*)d_in[4];
    const float* W3 = (const float*)d_in[5];
    const float* b3 = (const float*)d_in[6];
    const float* W4 = (const float*)d_in[7];
    const float* b4 = (const float*)d_in[8];
    float* out = (float*)d_out;

    const int WID = in_sizes[2];        // 512
    const int IN  = in_sizes[1] / WID;  // 256
    const int B   = in_sizes[0] / IN;   // 1024

    float *whi, *wlo, *ahi, *alo, *hlin, *hmax, *act;
    cudaGetSymbolAddress((void**)&whi, g_Whi);
    cudaGetSymbolAddress((void**)&wlo, g_Wlo);
    cudaGetSymbolAddress((void**)&ahi, g_Ahi);
    cudaGetSymbolAddress((void**)&alo, g_Alo);
    cudaGetSymbolAddress((void**)&hlin, g_Hlin);
    cudaGetSymbolAddress((void**)&hmax, g_Hmax);
    cudaGetSymbolAddress((void**)&act, g_act);

    cudaFuncSetAttribute(layer_fused<256>,
                         cudaFuncAttributeMaxDynamicSharedMemorySize, SMEM_BYTES);
    cudaFuncSetAttribute(layer_fused<512>,
                         cudaFuncAttributeMaxDynamicSharedMemorySize, SMEM_BYTES);

    const dim3 blk(256);
    const dim3 lgrid(MAXK_BLOCKS + 64);
    const int nW1 = WID * IN;
    const int nW  = WID * WID;
    const int nX  = B * IN;
    const int nH  = B * WID;

    // Layer 1
    split_kernel<<<(nW1 / 4 + 255) / 256, blk>>>(W1, whi, wlo, nW1 / 4);
    split_kernel<<<(nX / 4 + 255) / 256, blk>>>(x, ahi, alo, nX / 4);
    layer_fused<256><<<lgrid, blk, SMEM_BYTES>>>(x, ahi, alo, W1, whi, wlo, b1,
                                                 hlin, hmax, WID);
    combine_split_kernel<<<(nH / 4 + 255) / 256, blk>>>(hlin, hmax, act, ahi, alo, nH / 4);
    // Layer 2
    split_kernel<<<(nW / 4 + 255) / 256, blk>>>(W2, whi, wlo, nW / 4);
    layer_fused<512><<<lgrid, blk, SMEM_BYTES>>>(act, ahi, alo, W2, whi, wlo, b2,
                                                 hlin, hmax, WID);
    combine_split_kernel<<<(nH / 4 + 255) / 256, blk>>>(hlin, hmax, act, ahi, alo, nH / 4);
    // Layer 3
    split_kernel<<<(nW / 4 + 255) / 256, blk>>>(W3, whi, wlo, nW / 4);
    layer_fused<512><<<lgrid, blk, SMEM_BYTES>>>(act, ahi, alo, W3, whi, wlo, b3,
                                                 hlin, hmax, WID);
    combine_split_kernel<<<(nH / 4 + 255) / 256, blk>>>(hlin, hmax, act, ahi, alo, nH / 4);
    // Layer 4
    layer4_kernel<<<B / 8, blk>>>(act, W4, b4, out, B);
}

// round 9
// speedup vs baseline: 1.2586x; 1.2586x over previous
#include <cuda_runtime.h>
#include <math_constants.h>
#include <cstdint>

// ---------------------------------------------------------------------------
// Net_40312563041045: 4-layer max-tempered MLP
//   h = 0.8 * (X @ W^T) + 0.2 * max_k(W[o,k] * x[b,k]) + b
// B=1024, 256 -> 512 -> 512 -> 512 -> 1, fp32.
//
// R9: homogeneous fused blocks. 128 blocks x 512 threads; each block computes
// its 64x64 tile's MAX term (CUDA cores: MUL2+FMNMX, no FADD chain) AND its
// LINEAR term (legacy mma.sync m16n8k8 tf32, 3-pass hi/lo split = fp32-grade),
// then fuses combine + bias + tf32 re-split in the epilogue. One prep kernel
// does all W/x splits. 5 launches total, no combine glue.
// ---------------------------------------------------------------------------

#define BETA 0.2f
#define NEG_INF __int_as_float(0xff800000)
#define TILE_F 2304              // 64 * 36 floats per staged tile
#define MXS_F  (12 * TILE_F)     // mx buffer offset (floats)
#define SMEM_BYTES 128000        // (12*2304 + 64*68) * 4

// ---------------- global scratch ------------------------------------------
__device__ float g_Xhi[1024 * 256], g_Xlo[1024 * 256];
__device__ float g_W1hi[512 * 256], g_W1lo[512 * 256];
__device__ float g_W2hi[512 * 512], g_W2lo[512 * 512];
__device__ float g_W3hi[512 * 512], g_W3lo[512 * 512];
__device__ float g_actA[1024 * 512], g_HiA[1024 * 512], g_LoA[1024 * 512];
__device__ float g_actB[1024 * 512], g_HiB[1024 * 512], g_LoB[1024 * 512];

// ---------------- helpers --------------------------------------------------
__device__ __forceinline__ unsigned smem_u32(const void* p) {
    return (unsigned)__cvta_generic_to_shared(p);
}
__device__ __forceinline__ void cp16(unsigned dst, const void* src) {
    asm volatile("cp.async.ca.shared.global [%0], [%1], 16;\n" :: "r"(dst), "l"(src));
}
__device__ __forceinline__ float tf32_of(float v) {
    uint32_t t;
    asm("cvt.rna.tf32.f32 %0, %1;" : "=r"(t) : "f"(v));
    return __uint_as_float(t);
}
__device__ __forceinline__ void mma_tf32(float c[4], const uint32_t a[4],
                                         const uint32_t b[2]) {
    asm volatile(
        "mma.sync.aligned.m16n8k8.row.col.f32.tf32.tf32.f32 "
        "{%0,%1,%2,%3}, {%4,%5,%6,%7}, {%8,%9}, {%0,%1,%2,%3};"
        : "+f"(c[0]), "+f"(c[1]), "+f"(c[2]), "+f"(c[3])
        : "r"(a[0]), "r"(a[1]), "r"(a[2]), "r"(a[3]), "r"(b[0]), "r"(b[1]));
}

// ---------------- prep: split x, W1, W2, W3 into tf32 hi/lo ----------------
// float4 ranges: x [0,65536) W1 [65536,98304) W2 [98304,163840) W3 [163840,229376)
__global__ void __launch_bounds__(256)
prep_kernel(const float* __restrict__ x, const float* __restrict__ W1,
            const float* __restrict__ W2, const float* __restrict__ W3)
{
    const int i = blockIdx.x * 256 + threadIdx.x;
    const float* src; float* hi; float* lo; int off;
    if (i < 65536)       { src = x;  hi = g_Xhi;  lo = g_Xlo;  off = i; }
    else if (i < 98304)  { src = W1; hi = g_W1hi; lo = g_W1lo; off = i - 65536; }
    else if (i < 163840) { src = W2; hi = g_W2hi; lo = g_W2lo; off = i - 98304; }
    else                 { src = W3; hi = g_W3hi; lo = g_W3lo; off = i - 163840; }
    float4 v = ((const float4*)src)[off];
    float4 h, l;
    h.x = tf32_of(v.x); l.x = tf32_of(v.x - h.x);
    h.y = tf32_of(v.y); l.y = tf32_of(v.y - h.y);
    h.z = tf32_of(v.z); l.z = tf32_of(v.z - h.z);
    h.w = tf32_of(v.w); l.w = tf32_of(v.w - h.w);
    ((float4*)hi)[off] = h;
    ((float4*)lo)[off] = l;
}

// ---------------- fused layer ----------------------------------------------
// 128 blocks (16 m x 8 n), 512 threads. Double-buffered 6-tile staging.
// smem floats: buf b: b*6*TILE_F + {XF,WF,XH,XL,WH,WL}*TILE_F; mxs @ MXS_F.
template <int K>
__global__ void __launch_bounds__(512, 1)
layer_fused(const float* __restrict__ Xf,
            const float* __restrict__ Xhi, const float* __restrict__ Xlo,
            const float* __restrict__ Wf,
            const float* __restrict__ Whi, const float* __restrict__ Wlo,
            const float* __restrict__ bias,
            float* __restrict__ act, float* __restrict__ Ahi,
            float* __restrict__ Alo, int O)
{
    extern __shared__ float smf[];
    const unsigned sb = smem_u32(smf);
    const int tid = threadIdx.x;
    const int wid = tid >> 5;
    const int lane = tid & 31;
    const int m0 = (blockIdx.x & 15) * 64;
    const int n0 = (blockIdx.x >> 4) * 64;

    // max-role mapping (R6-verified): rows wid*4+i, cols lane+32*j
    // gemm mapping: 4 wm x 4 wn warps; m16 x (2 x n8) per warp (R8-verified frags)
    const int wm = wid & 3;
    const int wn = wid >> 2;
    const int lr = lane >> 2;
    const int lw = lane & 3;

    // staging map: 512 threads x one 16B chunk per tile stream
    const int srow = tid >> 3;        // 0..63
    const int sc   = (tid & 7) * 4;   // 0,4,...,28

    const float* xf = Xf  + (size_t)(m0 + srow) * K + sc;
    const float* xh = Xhi + (size_t)(m0 + srow) * K + sc;
    const float* xl = Xlo + (size_t)(m0 + srow) * K + sc;
    const float* wf = Wf  + (size_t)(n0 + srow) * K + sc;
    const float* wh = Whi + (size_t)(n0 + srow) * K + sc;
    const float* wl = Wlo + (size_t)(n0 + srow) * K + sc;

    float mx[4][2];
#pragma unroll
    for (int i = 0; i < 4; i++) { mx[i][0] = NEG_INF; mx[i][1] = NEG_INF; }
    float acc[2][4];
#pragma unroll
    for (int nt = 0; nt < 2; nt++)
#pragma unroll
        for (int e = 0; e < 4; e++) acc[nt][e] = 0.0f;

    const unsigned dstoff = (unsigned)(srow * 36 + sc) * 4;
    const int NCH = K / 32;

    // prologue: chunk 0 -> buf 0
    cp16(sb + dstoff,                      xf);
    cp16(sb + TILE_F * 4u + dstoff,        wf);
    cp16(sb + 2u * TILE_F * 4u + dstoff,   xh);
    cp16(sb + 3u * TILE_F * 4u + dstoff,   xl);
    cp16(sb + 4u * TILE_F * 4u + dstoff,   wh);
    cp16(sb + 5u * TILE_F * 4u + dstoff,   wl);
    asm volatile("cp.async.commit_group;\n");

    for (int c = 0; c < NCH; ++c) {
        const int buf = c & 1;
        if (c + 1 < NCH) {
            const unsigned bb = (unsigned)((buf ^ 1) * 6 * TILE_F) * 4u;
            const int k0 = (c + 1) * 32;
            cp16(sb + bb + dstoff,                    xf + k0);
            cp16(sb + bb + TILE_F * 4u + dstoff,      wf + k0);
            cp16(sb + bb + 2u * TILE_F * 4u + dstoff, xh + k0);
            cp16(sb + bb + 3u * TILE_F * 4u + dstoff, xl + k0);
            cp16(sb + bb + 4u * TILE_F * 4u + dstoff, wh + k0);
            cp16(sb + bb + 5u * TILE_F * 4u + dstoff, wl + k0);
            asm volatile("cp.async.commit_group;\n");
            asm volatile("cp.async.wait_group 1;\n");
        } else {
            asm volatile("cp.async.wait_group 0;\n");
        }
        __syncthreads();

        const float* XF = smf + buf * 6 * TILE_F;
        const float* WF = XF + TILE_F;
        const uint32_t* XH = (const uint32_t*)(XF + 2 * TILE_F);
        const uint32_t* XL = (const uint32_t*)(XF + 3 * TILE_F);
        const uint32_t* WH = (const uint32_t*)(XF + 4 * TILE_F);
        const uint32_t* WL = (const uint32_t*)(XF + 5 * TILE_F);

        // ---- MAX term: MUL2 + FMNMX only ----
#pragma unroll
        for (int kk = 0; kk < 32; kk += 4) {
            ulonglong2 xp[4], wp[2];
#pragma unroll
            for (int i = 0; i < 4; i++)
                xp[i] = *(const ulonglong2*)&XF[(wid * 4 + i) * 36 + kk];
#pragma unroll
            for (int j = 0; j < 2; j++)
                wp[j] = *(const ulonglong2*)&WF[(lane + 32 * j) * 36 + kk];
#pragma unroll
            for (int i = 0; i < 4; i++)
#pragma unroll
                for (int j = 0; j < 2; j++) {
                    asm("{\n\t.reg .b64 p;\n\t.reg .f32 plo, phi;\n\t"
                        "mul.rn.f32x2 p, %1, %2;\n\t"
                        "mov.b64 {plo, phi}, p;\n\t"
                        "max.f32 %0, %0, plo;\n\t"
                        "max.f32 %0, %0, phi;\n\t}"
                        : "+f"(mx[i][j]) : "l"(xp[i].x), "l"(wp[j].x));
                    asm("{\n\t.reg .b64 p;\n\t.reg .f32 plo, phi;\n\t"
                        "mul.rn.f32x2 p, %1, %2;\n\t"
                        "mov.b64 {plo, phi}, p;\n\t"
                        "max.f32 %0, %0, plo;\n\t"
                        "max.f32 %0, %0, phi;\n\t}"
                        : "+f"(mx[i][j]) : "l"(xp[i].y), "l"(wp[j].y));
                }
        }

        // ---- LINEAR term: mma.sync tf32 3-pass ----
#pragma unroll
        for (int kc = 0; kc < 32; kc += 8) {
            uint32_t ah[4], al[4];
            {
                const int base = (wm * 16 + lr) * 36 + kc + lw;
                ah[0] = XH[base];           ah[1] = XH[base + 8 * 36];
                ah[2] = XH[base + 4];       ah[3] = XH[base + 8 * 36 + 4];
                al[0] = XL[base];           al[1] = XL[base + 8 * 36];
                al[2] = XL[base + 4];       al[3] = XL[base + 8 * 36 + 4];
            }
#pragma unroll
            for (int nt = 0; nt < 2; nt++) {
                const int base = (wn * 16 + nt * 8 + lr) * 36 + kc + lw;
                uint32_t bh[2] = { WH[base], WH[base + 4] };
                uint32_t bl[2] = { WL[base], WL[base + 4] };
                mma_tf32(acc[nt], ah, bh);
                mma_tf32(acc[nt], ah, bl);
                mma_tf32(acc[nt], al, bh);
            }
        }
        __syncthreads();
    }

    // ---- epilogue: combine max + linear + bias, write act + hi/lo split ----
    float* mxs = smf + MXS_F;   // [64][68]
#pragma unroll
    for (int i = 0; i < 4; i++)
#pragma unroll
        for (int j = 0; j < 2; j++)
            mxs[(wid * 4 + i) * 68 + lane + 32 * j] = BETA * mx[i][j];
    __syncthreads();

    const int r0 = wm * 16 + lr;
#pragma unroll
    for (int nt = 0; nt < 2; nt++) {
        const int cc = wn * 16 + nt * 8 + lw * 2;
        const float2 bia = *(const float2*)&bias[n0 + cc];

        float a0 = 0.8f * acc[nt][0] + bia.x + mxs[r0 * 68 + cc];
        float a1 = 0.8f * acc[nt][1] + bia.y + mxs[r0 * 68 + cc + 1];
        float a2 = 0.8f * acc[nt][2] + bia.x + mxs[(r0 + 8) * 68 + cc];
        float a3 = 0.8f * acc[nt][3] + bia.y + mxs[(r0 + 8) * 68 + cc + 1];

        const size_t o0 = (size_t)(m0 + r0) * O + n0 + cc;
        const size_t o1 = (size_t)(m0 + r0 + 8) * O + n0 + cc;
        *(float2*)&act[o0] = make_float2(a0, a1);
        *(float2*)&act[o1] = make_float2(a2, a3);

        float h0 = tf32_of(a0), h1 = tf32_of(a1), h2 = tf32_of(a2), h3 = tf32_of(a3);
        *(float2*)&Ahi[o0] = make_float2(h0, h1);
        *(float2*)&Ahi[o1] = make_float2(h2, h3);
        *(float2*)&Alo[o0] = make_float2(tf32_of(a0 - h0), tf32_of(a1 - h1));
        *(float2*)&Alo[o1] = make_float2(tf32_of(a2 - h2), tf32_of(a3 - h3));
    }
}

// ---------------- final layer ----------------------------------------------
__global__ void __launch_bounds__(256)
layer4_kernel(const float* __restrict__ X, const float* __restrict__ W,
              const float* __restrict__ bias, float* __restrict__ out, int B)
{
    const int row = blockIdx.x * 8 + (threadIdx.x >> 5);
    const int lane = threadIdx.x & 31;
    if (row >= B) return;

    const float4* xr = (const float4*)(X + (size_t)row * 512);
    const float4* wr = (const float4*)W;

    float acc = 0.0f;
    float mx = -CUDART_INF_F;
#pragma unroll
    for (int it = 0; it < 4; ++it) {
        float4 x = xr[lane + 32 * it];
        float4 w = wr[lane + 32 * it];
        float p0 = x.x * w.x, p1 = x.y * w.y, p2 = x.z * w.z, p3 = x.w * w.w;
        acc += (p0 + p1) + (p2 + p3);
        mx = fmaxf(fmaxf(mx, fmaxf(p0, p1)), fmaxf(p2, p3));
    }
#pragma unroll
    for (int o = 16; o > 0; o >>= 1) {
        acc += __shfl_xor_sync(0xffffffff, acc, o);
        mx = fmaxf(mx, __shfl_xor_sync(0xffffffff, mx, o));
    }
    if (lane == 0)
        out[row] = (1.0f - BETA) * acc + BETA * mx + bias[0];
}

// ---------------- launch ----------------------------------------------------
extern "C" void kernel_launch(void* const* d_in, const int* in_sizes, int n_in,
                              void* d_out, int out_size)
{
    const float* x  = (const float*)d_in[0];
    const float* W1 = (const float*)d_in[1];
    const float* b1 = (const float*)d_in[2];
    const float* W2 = (const float*)d_in[3];
    const float* b2 = (const float*)d_in[4];
    const float* W3 = (const float*)d_in[5];
    const float* b3 = (const float*)d_in[6];
    const float* W4 = (const float*)d_in[7];
    const float* b4 = (const float*)d_in[8];
    float* out = (float*)d_out;

    const int WID = in_sizes[2];        // 512
    const int IN  = in_sizes[1] / WID;  // 256
    const int B   = in_sizes[0] / IN;   // 1024

    float *xhi, *xlo, *w1h, *w1l, *w2h, *w2l, *w3h, *w3l;
    float *actA, *hiA, *loA, *actB, *hiB, *loB;
    cudaGetSymbolAddress((void**)&xhi, g_Xhi);
    cudaGetSymbolAddress((void**)&xlo, g_Xlo);
    cudaGetSymbolAddress((void**)&w1h, g_W1hi);
    cudaGetSymbolAddress((void**)&w1l, g_W1lo);
    cudaGetSymbolAddress((void**)&w2h, g_W2hi);
    cudaGetSymbolAddress((void**)&w2l, g_W2lo);
    cudaGetSymbolAddress((void**)&w3h, g_W3hi);
    cudaGetSymbolAddress((void**)&w3l, g_W3lo);
    cudaGetSymbolAddress((void**)&actA, g_actA);
    cudaGetSymbolAddress((void**)&hiA, g_HiA);
    cudaGetSymbolAddress((void**)&loA, g_LoA);
    cudaGetSymbolAddress((void**)&actB, g_actB);
    cudaGetSymbolAddress((void**)&hiB, g_HiB);
    cudaGetSymbolAddress((void**)&loB, g_LoB);

    cudaFuncSetAttribute(layer_fused<256>,
                         cudaFuncAttributeMaxDynamicSharedMemorySize, SMEM_BYTES);
    cudaFuncSetAttribute(layer_fused<512>,
                         cudaFuncAttributeMaxDynamicSharedMemorySize, SMEM_BYTES);

    // prep: split x, W1, W2, W3 (229376 float4s / 256 = 896 blocks)
    prep_kernel<<<896, 256>>>(x, W1, W2, W3);

    const dim3 lgrid(128);
    const dim3 lblk(512);
    layer_fused<256><<<lgrid, lblk, SMEM_BYTES>>>(x, xhi, xlo, W1, w1h, w1l, b1,
                                                  actA, hiA, loA, WID);
    layer_fused<512><<<lgrid, lblk, SMEM_BYTES>>>(actA, hiA, loA, W2, w2h, w2l, b2,
                                                  actB, hiB, loB, WID);
    layer_fused<512><<<lgrid, lblk, SMEM_BYTES>>>(actB, hiB, loB, W3, w3h, w3l, b3,
                                                  actA, hiA, loA, WID);
    layer4_kernel<<<B / 8, 256>>>(actA, W4, b4, out, B);
}

// round 10
// speedup vs baseline: 1.3669x; 1.0861x over previous
#include <cuda_runtime.h>
#include <math_constants.h>
#include <cstdint>

// ---------------------------------------------------------------------------
// Net_40312563041045: 4-layer max-tempered MLP
//   h = 0.8 * (X @ W^T) + 0.2 * max_k(W[o,k] * x[b,k]) + b
// B=1024, 256 -> 512 -> 512 -> 512 -> 1, fp32.
//
// R10: warp-specialized fused layer. 128 blocks x 512 threads:
//   warps 0-7  (256 thr): MAX term, 64x64 tile, TM4xTN4 (2 B/triple LDS)
//   warps 8-15 (256 thr): LINEAR term, mma.sync m16n8k8 tf32 3-pass hi/lo
// R9 measured LDS-bound (L1 63%): this cuts LDS/chunk 703KB -> 408KB.
// Epilogue: gemm warps combine 0.8*lin + bias + mxs(smem) and emit
// act + tf32 hi/lo re-split. One prep kernel splits x/W1/W2/W3.
// ---------------------------------------------------------------------------

#define BETA 0.2f
#define NEG_INF __int_as_float(0xff800000)
#define TILE_F 2304              // 64 * 36 floats per staged tile
#define SMEM_BYTES 110592        // 2 bufs * 6 tiles * 2304 * 4B

// ---------------- global scratch ------------------------------------------
__device__ float g_Xhi[1024 * 256], g_Xlo[1024 * 256];
__device__ float g_W1hi[512 * 256], g_W1lo[512 * 256];
__device__ float g_W2hi[512 * 512], g_W2lo[512 * 512];
__device__ float g_W3hi[512 * 512], g_W3lo[512 * 512];
__device__ float g_actA[1024 * 512], g_HiA[1024 * 512], g_LoA[1024 * 512];
__device__ float g_actB[1024 * 512], g_HiB[1024 * 512], g_LoB[1024 * 512];

// ---------------- helpers --------------------------------------------------
__device__ __forceinline__ unsigned smem_u32(const void* p) {
    return (unsigned)__cvta_generic_to_shared(p);
}
__device__ __forceinline__ void cp16(unsigned dst, const void* src) {
    asm volatile("cp.async.ca.shared.global [%0], [%1], 16;\n" :: "r"(dst), "l"(src));
}
__device__ __forceinline__ float tf32_of(float v) {
    uint32_t t;
    asm("cvt.rna.tf32.f32 %0, %1;" : "=r"(t) : "f"(v));
    return __uint_as_float(t);
}
__device__ __forceinline__ void mma_tf32(float c[4], const uint32_t a[4],
                                         const uint32_t b[2]) {
    asm volatile(
        "mma.sync.aligned.m16n8k8.row.col.f32.tf32.tf32.f32 "
        "{%0,%1,%2,%3}, {%4,%5,%6,%7}, {%8,%9}, {%0,%1,%2,%3};"
        : "+f"(c[0]), "+f"(c[1]), "+f"(c[2]), "+f"(c[3])
        : "r"(a[0]), "r"(a[1]), "r"(a[2]), "r"(a[3]), "r"(b[0]), "r"(b[1]));
}

// ---------------- prep: split x, W1, W2, W3 into tf32 hi/lo ----------------
__global__ void __launch_bounds__(256)
prep_kernel(const float* __restrict__ x, const float* __restrict__ W1,
            const float* __restrict__ W2, const float* __restrict__ W3)
{
    const int i = blockIdx.x * 256 + threadIdx.x;
    const float* src; float* hi; float* lo; int off;
    if (i < 65536)       { src = x;  hi = g_Xhi;  lo = g_Xlo;  off = i; }
    else if (i < 98304)  { src = W1; hi = g_W1hi; lo = g_W1lo; off = i - 65536; }
    else if (i < 163840) { src = W2; hi = g_W2hi; lo = g_W2lo; off = i - 98304; }
    else                 { src = W3; hi = g_W3hi; lo = g_W3lo; off = i - 163840; }
    float4 v = ((const float4*)src)[off];
    float4 h, l;
    h.x = tf32_of(v.x); l.x = tf32_of(v.x - h.x);
    h.y = tf32_of(v.y); l.y = tf32_of(v.y - h.y);
    h.z = tf32_of(v.z); l.z = tf32_of(v.z - h.z);
    h.w = tf32_of(v.w); l.w = tf32_of(v.w - h.w);
    ((float4*)hi)[off] = h;
    ((float4*)lo)[off] = l;
}

// ---------------- warp-specialized fused layer ------------------------------
// 128 blocks (16 m x 8 n), 512 threads. Buffer b at smf + b*6*TILE_F:
//   tiles: XF +0, WF +1, XH +2, XL +3, WH +4, WL +5 (each 64x36 floats).
// mxs[64][68] aliases buffer 0 after the final (buf=1) chunk.
template <int K>
__global__ void __launch_bounds__(512, 1)
layer_fused(const float* __restrict__ Xf,
            const float* __restrict__ Xhi, const float* __restrict__ Xlo,
            const float* __restrict__ Wf,
            const float* __restrict__ Whi, const float* __restrict__ Wlo,
            const float* __restrict__ bias,
            float* __restrict__ act, float* __restrict__ Ahi,
            float* __restrict__ Alo, int O)
{
    extern __shared__ float smf[];
    const unsigned sb = smem_u32(smf);
    const int tid = threadIdx.x;
    const int wid = tid >> 5;
    const int lane = tid & 31;
    const int m0 = (blockIdx.x & 15) * 64;
    const int n0 = (blockIdx.x >> 4) * 64;

    // staging: 512 threads x one 16B chunk per tile stream
    const int srow = tid >> 3;
    const int sc   = (tid & 7) * 4;
    const unsigned dstoff = (unsigned)(srow * 36 + sc) * 4;

    const float* xf = Xf  + (size_t)(m0 + srow) * K + sc;
    const float* xh = Xhi + (size_t)(m0 + srow) * K + sc;
    const float* xl = Xlo + (size_t)(m0 + srow) * K + sc;
    const float* wf = Wf  + (size_t)(n0 + srow) * K + sc;
    const float* wh = Whi + (size_t)(n0 + srow) * K + sc;
    const float* wl = Wlo + (size_t)(n0 + srow) * K + sc;

    // max-role mapping (R2-verified, threads 0-255)
    const int tcol = tid & 15;
    const int trow = tid >> 4;          // 0..15 for tid < 256
    // gemm-role mapping (R8-verified frags, warps 8-15)
    const int gw = wid - 8;
    const int wm = gw & 1;              // 2 row-groups of 32
    const int wn = gw >> 1;             // 4 col-groups of 16
    const int lr = lane >> 2;
    const int lw = lane & 3;

    float mx[4][4];
#pragma unroll
    for (int i = 0; i < 4; i++)
#pragma unroll
        for (int j = 0; j < 4; j++) mx[i][j] = NEG_INF;
    float acc[2][2][4];
#pragma unroll
    for (int mt = 0; mt < 2; mt++)
#pragma unroll
        for (int nt = 0; nt < 2; nt++)
#pragma unroll
            for (int e = 0; e < 4; e++) acc[mt][nt][e] = 0.0f;

    const int NCH = K / 32;

    // prologue: chunk 0 -> buffer 0
    cp16(sb + dstoff,                    xf);
    cp16(sb + TILE_F * 4u + dstoff,      wf);
    cp16(sb + 2u * TILE_F * 4u + dstoff, xh);
    cp16(sb + 3u * TILE_F * 4u + dstoff, xl);
    cp16(sb + 4u * TILE_F * 4u + dstoff, wh);
    cp16(sb + 5u * TILE_F * 4u + dstoff, wl);
    asm volatile("cp.async.commit_group;\n");

    for (int c = 0; c < NCH; ++c) {
        const int buf = c & 1;
        if (c + 1 < NCH) {
            const unsigned bb = (unsigned)((buf ^ 1) * 6 * TILE_F) * 4u;
            const int k0 = (c + 1) * 32;
            cp16(sb + bb + dstoff,                    xf + k0);
            cp16(sb + bb + TILE_F * 4u + dstoff,      wf + k0);
            cp16(sb + bb + 2u * TILE_F * 4u + dstoff, xh + k0);
            cp16(sb + bb + 3u * TILE_F * 4u + dstoff, xl + k0);
            cp16(sb + bb + 4u * TILE_F * 4u + dstoff, wh + k0);
            cp16(sb + bb + 5u * TILE_F * 4u + dstoff, wl + k0);
            asm volatile("cp.async.commit_group;\n");
            asm volatile("cp.async.wait_group 1;\n");
        } else {
            asm volatile("cp.async.wait_group 0;\n");
        }
        __syncthreads();

        const float* XF = smf + buf * 6 * TILE_F;

        if (wid < 8) {
            // ---------------- MAX warps: MUL2 + FMNMX ----------------------
            const float* WF = XF + TILE_F;
#pragma unroll
            for (int kk = 0; kk < 32; kk += 4) {
                ulonglong2 xp[4], wp[4];
#pragma unroll
                for (int i = 0; i < 4; i++)
                    xp[i] = *(const ulonglong2*)&XF[(trow * 4 + i) * 36 + kk];
#pragma unroll
                for (int j = 0; j < 4; j++)
                    wp[j] = *(const ulonglong2*)&WF[(tcol + 16 * j) * 36 + kk];
#pragma unroll
                for (int i = 0; i < 4; i++)
#pragma unroll
                    for (int j = 0; j < 4; j++) {
                        asm("{\n\t.reg .b64 p;\n\t.reg .f32 plo, phi;\n\t"
                            "mul.rn.f32x2 p, %1, %2;\n\t"
                            "mov.b64 {plo, phi}, p;\n\t"
                            "max.f32 %0, %0, plo;\n\t"
                            "max.f32 %0, %0, phi;\n\t}"
                            : "+f"(mx[i][j]) : "l"(xp[i].x), "l"(wp[j].x));
                        asm("{\n\t.reg .b64 p;\n\t.reg .f32 plo, phi;\n\t"
                            "mul.rn.f32x2 p, %1, %2;\n\t"
                            "mov.b64 {plo, phi}, p;\n\t"
                            "max.f32 %0, %0, plo;\n\t"
                            "max.f32 %0, %0, phi;\n\t}"
                            : "+f"(mx[i][j]) : "l"(xp[i].y), "l"(wp[j].y));
                    }
            }
        } else {
            // ---------------- GEMM warps: mma.sync tf32 3-pass -------------
            const uint32_t* XH = (const uint32_t*)(XF + 2 * TILE_F);
            const uint32_t* XL = (const uint32_t*)(XF + 3 * TILE_F);
            const uint32_t* WH = (const uint32_t*)(XF + 4 * TILE_F);
            const uint32_t* WL = (const uint32_t*)(XF + 5 * TILE_F);
#pragma unroll
            for (int kc = 0; kc < 32; kc += 8) {
                uint32_t ah[2][4], al[2][4];
#pragma unroll
                for (int mt = 0; mt < 2; mt++) {
                    const int base = (wm * 32 + mt * 16 + lr) * 36 + kc + lw;
                    ah[mt][0] = XH[base];     ah[mt][1] = XH[base + 8 * 36];
                    ah[mt][2] = XH[base + 4]; ah[mt][3] = XH[base + 8 * 36 + 4];
                    al[mt][0] = XL[base];     al[mt][1] = XL[base + 8 * 36];
                    al[mt][2] = XL[base + 4]; al[mt][3] = XL[base + 8 * 36 + 4];
                }
#pragma unroll
                for (int nt = 0; nt < 2; nt++) {
                    const int base = (wn * 16 + nt * 8 + lr) * 36 + kc + lw;
                    uint32_t bh[2] = { WH[base], WH[base + 4] };
                    uint32_t bl[2] = { WL[base], WL[base + 4] };
#pragma unroll
                    for (int mt = 0; mt < 2; mt++) {
                        mma_tf32(acc[mt][nt], ah[mt], bh);
                        mma_tf32(acc[mt][nt], ah[mt], bl);
                        mma_tf32(acc[mt][nt], al[mt], bh);
                    }
                }
            }
        }
        __syncthreads();
    }

    // ---- epilogue: max warps publish mx; gemm warps combine + store -------
    float* mxs = smf;   // [64][68]; aliases buffer 0 (free: last chunk = buf 1)
    if (wid < 8) {
#pragma unroll
        for (int i = 0; i < 4; i++)
#pragma unroll
            for (int j = 0; j < 4; j++)
                mxs[(trow * 4 + i) * 68 + tcol + 16 * j] = BETA * mx[i][j];
    }
    __syncthreads();

    if (wid >= 8) {
#pragma unroll
        for (int mt = 0; mt < 2; mt++) {
            const int r0 = wm * 32 + mt * 16 + lr;
#pragma unroll
            for (int nt = 0; nt < 2; nt++) {
                const int cc = wn * 16 + nt * 8 + lw * 2;
                const float2 bia = *(const float2*)&bias[n0 + cc];

                float a0 = 0.8f * acc[mt][nt][0] + bia.x + mxs[r0 * 68 + cc];
                float a1 = 0.8f * acc[mt][nt][1] + bia.y + mxs[r0 * 68 + cc + 1];
                float a2 = 0.8f * acc[mt][nt][2] + bia.x + mxs[(r0 + 8) * 68 + cc];
                float a3 = 0.8f * acc[mt][nt][3] + bia.y + mxs[(r0 + 8) * 68 + cc + 1];

                const size_t o0 = (size_t)(m0 + r0) * O + n0 + cc;
                const size_t o1 = (size_t)(m0 + r0 + 8) * O + n0 + cc;
                *(float2*)&act[o0] = make_float2(a0, a1);
                *(float2*)&act[o1] = make_float2(a2, a3);

                float h0 = tf32_of(a0), h1 = tf32_of(a1);
                float h2 = tf32_of(a2), h3 = tf32_of(a3);
                *(float2*)&Ahi[o0] = make_float2(h0, h1);
                *(float2*)&Ahi[o1] = make_float2(h2, h3);
                *(float2*)&Alo[o0] = make_float2(tf32_of(a0 - h0), tf32_of(a1 - h1));
                *(float2*)&Alo[o1] = make_float2(tf32_of(a2 - h2), tf32_of(a3 - h3));
            }
        }
    }
}

// ---------------- final layer ----------------------------------------------
__global__ void __launch_bounds__(256)
layer4_kernel(const float* __restrict__ X, const float* __restrict__ W,
              const float* __restrict__ bias, float* __restrict__ out, int B)
{
    const int row = blockIdx.x * 8 + (threadIdx.x >> 5);
    const int lane = threadIdx.x & 31;
    if (row >= B) return;

    const float4* xr = (const float4*)(X + (size_t)row * 512);
    const float4* wr = (const float4*)W;

    float acc = 0.0f;
    float mx = -CUDART_INF_F;
#pragma unroll
    for (int it = 0; it < 4; ++it) {
        float4 x = xr[lane + 32 * it];
        float4 w = wr[lane + 32 * it];
        float p0 = x.x * w.x, p1 = x.y * w.y, p2 = x.z * w.z, p3 = x.w * w.w;
        acc += (p0 + p1) + (p2 + p3);
        mx = fmaxf(fmaxf(mx, fmaxf(p0, p1)), fmaxf(p2, p3));
    }
#pragma unroll
    for (int o = 16; o > 0; o >>= 1) {
        acc += __shfl_xor_sync(0xffffffff, acc, o);
        mx = fmaxf(mx, __shfl_xor_sync(0xffffffff, mx, o));
    }
    if (lane == 0)
        out[row] = (1.0f - BETA) * acc + BETA * mx + bias[0];
}

// ---------------- launch ----------------------------------------------------
extern "C" void kernel_launch(void* const* d_in, const int* in_sizes, int n_in,
                              void* d_out, int out_size)
{
    const float* x  = (const float*)d_in[0];
    const float* W1 = (const float*)d_in[1];
    const float* b1 = (const float*)d_in[2];
    const float* W2 = (const float*)d_in[3];
    const float* b2 = (const float*)d_in[4];
    const float* W3 = (const float*)d_in[5];
    const float* b3 = (const float*)d_in[6];
    const float* W4 = (const float*)d_in[7];
    const float* b4 = (const float*)d_in[8];
    float* out = (float*)d_out;

    const int WID = in_sizes[2];        // 512
    const int IN  = in_sizes[1] / WID;  // 256
    const int B   = in_sizes[0] / IN;   // 1024

    float *xhi, *xlo, *w1h, *w1l, *w2h, *w2l, *w3h, *w3l;
    float *actA, *hiA, *loA, *actB, *hiB, *loB;
    cudaGetSymbolAddress((void**)&xhi, g_Xhi);
    cudaGetSymbolAddress((void**)&xlo, g_Xlo);
    cudaGetSymbolAddress((void**)&w1h, g_W1hi);
    cudaGetSymbolAddress((void**)&w1l, g_W1lo);
    cudaGetSymbolAddress((void**)&w2h, g_W2hi);
    cudaGetSymbolAddress((void**)&w2l, g_W2lo);
    cudaGetSymbolAddress((void**)&w3h, g_W3hi);
    cudaGetSymbolAddress((void**)&w3l, g_W3lo);
    cudaGetSymbolAddress((void**)&actA, g_actA);
    cudaGetSymbolAddress((void**)&hiA, g_HiA);
    cudaGetSymbolAddress((void**)&loA, g_LoA);
    cudaGetSymbolAddress((void**)&actB, g_actB);
    cudaGetSymbolAddress((void**)&hiB, g_HiB);
    cudaGetSymbolAddress((void**)&loB, g_LoB);

    cudaFuncSetAttribute(layer_fused<256>,
                         cudaFuncAttributeMaxDynamicSharedMemorySize, SMEM_BYTES);
    cudaFuncSetAttribute(layer_fused<512>,
                         cudaFuncAttributeMaxDynamicSharedMemorySize, SMEM_BYTES);

    prep_kernel<<<896, 256>>>(x, W1, W2, W3);

    const dim3 lgrid(128);
    const dim3 lblk(512);
    layer_fused<256><<<lgrid, lblk, SMEM_BYTES>>>(x, xhi, xlo, W1, w1h, w1l, b1,
                                                  actA, hiA, loA, WID);
    layer_fused<512><<<lgrid, lblk, SMEM_BYTES>>>(actA, hiA, loA, W2, w2h, w2l, b2,
                                                  actB, hiB, loB, WID);
    layer_fused<512><<<lgrid, lblk, SMEM_BYTES>>>(actB, hiB, loB, W3, w3h, w3l, b3,
                                                  actA, hiA, loA, WID);
    layer4_kernel<<<B / 8, 256>>>(actA, W4, b4, out, B);
}

// round 11
// speedup vs baseline: 1.4218x; 1.0401x over previous
#include <cuda_runtime.h>
#include <math_constants.h>
#include <cstdint>

// ---------------------------------------------------------------------------
// Net_40312563041045: 4-layer max-tempered MLP
//   h = 0.8 * (X @ W^T) + 0.2 * max_k(W[o,k] * x[b,k]) + b
// B=1024, 256 -> 512 -> 512 -> 512 -> 1, fp32.
//
// R11: derive tf32 hi/lo IN-REGISTER inside the gemm warps (no prep kernel,
// no hi/lo global buffers, stage only 2 fp32 tiles). Retile to 64x32 with
// 256 threads (4 max warps TM4xTN4 + 4 gemm warps mma.sync tf32 3-pass),
// grid=256, 2 blocks/SM so barrier/stage latency is covered.
// 4 launches total.
// ---------------------------------------------------------------------------

#define BETA 0.2f
#define NEG_INF __int_as_float(0xff800000)
#define XTILE_F 2304    // 64 rows * 36
#define WTILE_F 1152    // 32 rows * 36
#define BUF_F   3456    // XTILE_F + WTILE_F

__device__ float g_actA[1024 * 512];
__device__ float g_actB[1024 * 512];

__device__ __forceinline__ unsigned smem_u32(const void* p) {
    return (unsigned)__cvta_generic_to_shared(p);
}
__device__ __forceinline__ void cp16(unsigned dst, const void* src) {
    asm volatile("cp.async.ca.shared.global [%0], [%1], 16;\n" :: "r"(dst), "l"(src));
}
__device__ __forceinline__ float tf32_of(float v) {
    uint32_t t;
    asm("cvt.rna.tf32.f32 %0, %1;" : "=r"(t) : "f"(v));
    return __uint_as_float(t);
}
__device__ __forceinline__ void split_tf32(float f, uint32_t &h, uint32_t &l) {
    float hf = tf32_of(f);
    h = __float_as_uint(hf);
    l = __float_as_uint(tf32_of(f - hf));
}
__device__ __forceinline__ void mma_tf32(float c[4], const uint32_t a[4],
                                         const uint32_t b[2]) {
    asm volatile(
        "mma.sync.aligned.m16n8k8.row.col.f32.tf32.tf32.f32 "
        "{%0,%1,%2,%3}, {%4,%5,%6,%7}, {%8,%9}, {%0,%1,%2,%3};"
        : "+f"(c[0]), "+f"(c[1]), "+f"(c[2]), "+f"(c[3])
        : "r"(a[0]), "r"(a[1]), "r"(a[2]), "r"(a[3]), "r"(b[0]), "r"(b[1]));
}

// ---------------- fused warp-specialized layer ------------------------------
// Grid 256 = 16 (m: 64 rows) x 16 (n: 32 cols). 256 threads:
//   warps 0-3: MAX term, TM4 x TN4 (rows trow*4+i, cols tcol+8*j)
//   warps 4-7: LINEAR term, mma.sync m16n8k8 tf32 3-pass (in-register split)
// smem: smf[2][BUF_F]: X tile @0 (64x36), W tile @XTILE_F (32x36).
// mxs[64][36] aliases buffer 0 after the last chunk (last buf is always 1).
template <int K>
__global__ void __launch_bounds__(256, 2)
layer_fused(const float* __restrict__ Xf, const float* __restrict__ Wf,
            const float* __restrict__ bias, float* __restrict__ act, int O)
{
    __shared__ float smf[2][BUF_F];
    const unsigned sb = smem_u32(smf);
    const int tid = threadIdx.x;
    const int wid = tid >> 5;
    const int lane = tid & 31;
    const int m0 = (blockIdx.x & 15) * 64;
    const int n0 = (blockIdx.x >> 4) * 32;

    // staging: X 512 chunks (2/thread), W 256 chunks (1/thread)
    const int xrow = tid >> 2;          // 0..63
    const int xq   = (tid & 3) * 4;     // float col 0,4,8,12 (+16 for 2nd)
    const int wrow = tid >> 3;          // 0..31
    const int wq   = (tid & 7) * 4;     // float col 0..28

    const float* xg = Xf + (size_t)(m0 + xrow) * K + xq;
    const float* wg = Wf + (size_t)(n0 + wrow) * K + wq;

    // max-role mapping
    const int tcol = tid & 7;           // cols n0 + tcol + 8*j
    const int trow = tid >> 3;          // 0..15 (tid<128): rows m0 + trow*4+i
    // gemm-role mapping (R8/R10-verified fragment indices)
    const int gw = wid - 4;
    const int wm = gw & 1;              // 2 row-groups of 32
    const int wn = gw >> 1;             // 2 col-groups of 16
    const int lr = lane >> 2;
    const int lw = lane & 3;

    float mx[4][4];
#pragma unroll
    for (int i = 0; i < 4; i++)
#pragma unroll
        for (int j = 0; j < 4; j++) mx[i][j] = NEG_INF;
    float acc[2][2][4];
#pragma unroll
    for (int mt = 0; mt < 2; mt++)
#pragma unroll
        for (int nt = 0; nt < 2; nt++)
#pragma unroll
            for (int e = 0; e < 4; e++) acc[mt][nt][e] = 0.0f;

    const int NCH = K / 32;

    // prologue: chunk 0 -> buffer 0
    {
        const unsigned xoff = (unsigned)(xrow * 36 + xq) * 4;
        const unsigned woff = (unsigned)(XTILE_F + wrow * 36 + wq) * 4;
        cp16(sb + xoff,        xg);
        cp16(sb + xoff + 64,   xg + 16);   // +16 floats = +64 B dst, src +16
        cp16(sb + woff,        wg);
        asm volatile("cp.async.commit_group;\n");
    }

    for (int c = 0; c < NCH; ++c) {
        const int buf = c & 1;
        if (c + 1 < NCH) {
            const int k0 = (c + 1) * 32;
            const unsigned bb = (unsigned)((buf ^ 1) * BUF_F) * 4u;
            const unsigned xoff = bb + (unsigned)(xrow * 36 + xq) * 4;
            const unsigned woff = bb + (unsigned)(XTILE_F + wrow * 36 + wq) * 4;
            cp16(xoff + sb,      xg + k0);
            cp16(xoff + sb + 64, xg + k0 + 16);
            cp16(woff + sb,      wg + k0);
            asm volatile("cp.async.commit_group;\n");
            asm volatile("cp.async.wait_group 1;\n");
        } else {
            asm volatile("cp.async.wait_group 0;\n");
        }
        __syncthreads();

        const float* XF = smf[buf];
        const float* WF = smf[buf] + XTILE_F;

        if (wid < 4) {
            // -------- MAX warps: MUL2 + FMNMX only --------
#pragma unroll
            for (int kk = 0; kk < 32; kk += 4) {
                ulonglong2 xp[4], wp[4];
#pragma unroll
                for (int i = 0; i < 4; i++)
                    xp[i] = *(const ulonglong2*)&XF[(trow * 4 + i) * 36 + kk];
#pragma unroll
                for (int j = 0; j < 4; j++)
                    wp[j] = *(const ulonglong2*)&WF[(tcol + 8 * j) * 36 + kk];
#pragma unroll
                for (int i = 0; i < 4; i++)
#pragma unroll
                    for (int j = 0; j < 4; j++) {
                        asm("{\n\t.reg .b64 p;\n\t.reg .f32 plo, phi;\n\t"
                            "mul.rn.f32x2 p, %1, %2;\n\t"
                            "mov.b64 {plo, phi}, p;\n\t"
                            "max.f32 %0, %0, plo;\n\t"
                            "max.f32 %0, %0, phi;\n\t}"
                            : "+f"(mx[i][j]) : "l"(xp[i].x), "l"(wp[j].x));
                        asm("{\n\t.reg .b64 p;\n\t.reg .f32 plo, phi;\n\t"
                            "mul.rn.f32x2 p, %1, %2;\n\t"
                            "mov.b64 {plo, phi}, p;\n\t"
                            "max.f32 %0, %0, plo;\n\t"
                            "max.f32 %0, %0, phi;\n\t}"
                            : "+f"(mx[i][j]) : "l"(xp[i].y), "l"(wp[j].y));
                    }
            }
        } else {
            // -------- GEMM warps: in-register tf32 split + 3-pass mma -------
#pragma unroll
            for (int kc = 0; kc < 32; kc += 8) {
                uint32_t ah[2][4], al[2][4];
#pragma unroll
                for (int mt = 0; mt < 2; mt++) {
                    const int base = (wm * 32 + mt * 16 + lr) * 36 + kc + lw;
                    split_tf32(XF[base],          ah[mt][0], al[mt][0]);
                    split_tf32(XF[base + 8 * 36], ah[mt][1], al[mt][1]);
                    split_tf32(XF[base + 4],      ah[mt][2], al[mt][2]);
                    split_tf32(XF[base + 8 * 36 + 4], ah[mt][3], al[mt][3]);
                }
#pragma unroll
                for (int nt = 0; nt < 2; nt++) {
                    const int base = (wn * 16 + nt * 8 + lr) * 36 + kc + lw;
                    uint32_t bh[2], bl[2];
                    split_tf32(WF[base],     bh[0], bl[0]);
                    split_tf32(WF[base + 4], bh[1], bl[1]);
#pragma unroll
                    for (int mt = 0; mt < 2; mt++) {
                        mma_tf32(acc[mt][nt], ah[mt], bh);
                        mma_tf32(acc[mt][nt], ah[mt], bl);
                        mma_tf32(acc[mt][nt], al[mt], bh);
                    }
                }
            }
        }
        __syncthreads();
    }

    // ---- epilogue: max warps publish mx, gemm warps combine + store -------
    float* mxs = smf[0];   // [64][36]; buffer 0 free (last chunk uses buf 1)
    if (wid < 4) {
#pragma unroll
        for (int i = 0; i < 4; i++)
#pragma unroll
            for (int j = 0; j < 4; j++)
                mxs[(trow * 4 + i) * 36 + tcol + 8 * j] = BETA * mx[i][j];
    }
    __syncthreads();

    if (wid >= 4) {
#pragma unroll
        for (int mt = 0; mt < 2; mt++) {
            const int r0 = wm * 32 + mt * 16 + lr;
#pragma unroll
            for (int nt = 0; nt < 2; nt++) {
                const int cc = wn * 16 + nt * 8 + lw * 2;
                const float2 bia = *(const float2*)&bias[n0 + cc];

                float a0 = 0.8f * acc[mt][nt][0] + bia.x + mxs[r0 * 36 + cc];
                float a1 = 0.8f * acc[mt][nt][1] + bia.y + mxs[r0 * 36 + cc + 1];
                float a2 = 0.8f * acc[mt][nt][2] + bia.x + mxs[(r0 + 8) * 36 + cc];
                float a3 = 0.8f * acc[mt][nt][3] + bia.y + mxs[(r0 + 8) * 36 + cc + 1];

                const size_t o0 = (size_t)(m0 + r0) * O + n0 + cc;
                const size_t o1 = (size_t)(m0 + r0 + 8) * O + n0 + cc;
                *(float2*)&act[o0] = make_float2(a0, a1);
                *(float2*)&act[o1] = make_float2(a2, a3);
            }
        }
    }
}

// ---------------- final layer ----------------------------------------------
__global__ void __launch_bounds__(256)
layer4_kernel(const float* __restrict__ X, const float* __restrict__ W,
              const float* __restrict__ bias, float* __restrict__ out, int B)
{
    const int row = blockIdx.x * 8 + (threadIdx.x >> 5);
    const int lane = threadIdx.x & 31;
    if (row >= B) return;

    const float4* xr = (const float4*)(X + (size_t)row * 512);
    const float4* wr = (const float4*)W;

    float acc = 0.0f;
    float mx = -CUDART_INF_F;
#pragma unroll
    for (int it = 0; it < 4; ++it) {
        float4 x = xr[lane + 32 * it];
        float4 w = wr[lane + 32 * it];
        float p0 = x.x * w.x, p1 = x.y * w.y, p2 = x.z * w.z, p3 = x.w * w.w;
        acc += (p0 + p1) + (p2 + p3);
        mx = fmaxf(fmaxf(mx, fmaxf(p0, p1)), fmaxf(p2, p3));
    }
#pragma unroll
    for (int o = 16; o > 0; o >>= 1) {
        acc += __shfl_xor_sync(0xffffffff, acc, o);
        mx = fmaxf(mx, __shfl_xor_sync(0xffffffff, mx, o));
    }
    if (lane == 0)
        out[row] = (1.0f - BETA) * acc + BETA * mx + bias[0];
}

// ---------------- launch ----------------------------------------------------
extern "C" void kernel_launch(void* const* d_in, const int* in_sizes, int n_in,
                              void* d_out, int out_size)
{
    const float* x  = (const float*)d_in[0];
    const float* W1 = (const float*)d_in[1];
    const float* b1 = (const float*)d_in[2];
    const float* W2 = (const float*)d_in[3];
    const float* b2 = (const float*)d_in[4];
    const float* W3 = (const float*)d_in[5];
    const float* b3 = (const float*)d_in[6];
    const float* W4 = (const float*)d_in[7];
    const float* b4 = (const float*)d_in[8];
    float* out = (float*)d_out;

    const int WID = in_sizes[2];        // 512
    const int IN  = in_sizes[1] / WID;  // 256
    const int B   = in_sizes[0] / IN;   // 1024

    float *actA, *actB;
    cudaGetSymbolAddress((void**)&actA, g_actA);
    cudaGetSymbolAddress((void**)&actB, g_actB);

    const dim3 blk(256);
    const dim3 grid(256);   // 16 m-tiles x 16 n-tiles of 64x32

    layer_fused<256><<<grid, blk>>>(x,    W1, b1, actA, WID);
    layer_fused<512><<<grid, blk>>>(actA, W2, b2, actB, WID);
    layer_fused<512><<<grid, blk>>>(actB, W3, b3, actA, WID);
    layer4_kernel<<<B / 8, blk>>>(actA, W4, b4, out, B);
}

// round 12
// speedup vs baseline: 1.6743x; 1.1777x over previous
#include <cuda_runtime.h>
#include <math_constants.h>
#include <cuda_fp16.h>
#include <cstdint>

// ---------------------------------------------------------------------------
// Net_40312563041045: 4-layer max-tempered MLP
//   h = 0.8 * (X @ W^T) + 0.2 * max_k(W[o,k] * x[b,k]) + b
// B=1024, 256 -> 512 -> 512 -> 512 -> 1, fp32.
//
// R12: R11 skeleton + PACKED fp16 max term. Max warps consume fp16 tiles
// (converted in-kernel from the staged fp32 tiles) with mul.f16x2+max.f16x2:
// 2 triples per instruction pair, halving the dominant alu-pipe load.
// Gemm warps: unchanged verified mma.sync tf32 3-pass with in-register split.
// 64x32 tile, 256 threads (4 max + 4 gemm warps), grid 256, 2 blocks/SM.
// ---------------------------------------------------------------------------

#define BETA 0.2f
#define XTILE_F 2304    // 64 rows * 36 floats
#define BUF_F   3456    // X (64x36) + W (32x36)

__device__ float g_actA[1024 * 512];
__device__ float g_actB[1024 * 512];

__device__ __forceinline__ unsigned smem_u32(const void* p) {
    return (unsigned)__cvta_generic_to_shared(p);
}
__device__ __forceinline__ void cp16(unsigned dst, const void* src) {
    asm volatile("cp.async.ca.shared.global [%0], [%1], 16;\n" :: "r"(dst), "l"(src));
}
__device__ __forceinline__ float tf32_of(float v) {
    uint32_t t;
    asm("cvt.rna.tf32.f32 %0, %1;" : "=r"(t) : "f"(v));
    return __uint_as_float(t);
}
__device__ __forceinline__ void split_tf32(float f, uint32_t &h, uint32_t &l) {
    float hf = tf32_of(f);
    h = __float_as_uint(hf);
    l = __float_as_uint(tf32_of(f - hf));
}
__device__ __forceinline__ void mma_tf32(float c[4], const uint32_t a[4],
                                         const uint32_t b[2]) {
    asm volatile(
        "mma.sync.aligned.m16n8k8.row.col.f32.tf32.tf32.f32 "
        "{%0,%1,%2,%3}, {%4,%5,%6,%7}, {%8,%9}, {%0,%1,%2,%3};"
        : "+f"(c[0]), "+f"(c[1]), "+f"(c[2]), "+f"(c[3])
        : "r"(a[0]), "r"(a[1]), "r"(a[2]), "r"(a[3]), "r"(b[0]), "r"(b[1]));
}

// ---------------- fused warp-specialized layer ------------------------------
// Grid 256 = 16 (m: 64 rows) x 16 (n: 32 cols). 256 threads:
//   warps 0-3: MAX term in packed fp16 over converted tiles
//   warps 4-7: LINEAR term, mma.sync tf32 3-pass (in-register split)
template <int K>
__global__ void __launch_bounds__(256, 2)
layer_fused(const float* __restrict__ Xf, const float* __restrict__ Wf,
            const float* __restrict__ bias, float* __restrict__ act, int O)
{
    __shared__ float  smf[2][BUF_F];    // fp32 staging, double buffered
    __shared__ __half x16s[64 * 40];    // fp16 X tile (stride 40 halves)
    __shared__ __half w16s[32 * 40];    // fp16 W tile

    const unsigned sb = smem_u32(smf);
    const int tid = threadIdx.x;
    const int wid = tid >> 5;
    const int lane = tid & 31;
    const int m0 = (blockIdx.x & 15) * 64;
    const int n0 = (blockIdx.x >> 4) * 32;

    // staging: X 512 chunks (2/thread), W 256 chunks (1/thread)
    const int xrow = tid >> 2;
    const int xq   = (tid & 3) * 4;
    const int wrow = tid >> 3;
    const int wq   = (tid & 7) * 4;
    const float* xg = Xf + (size_t)(m0 + xrow) * K + xq;
    const float* wg = Wf + (size_t)(n0 + wrow) * K + wq;

    // max-role mapping (threads 0-127): rows trow*4+i, cols tcol+8*j
    const int tcol = tid & 7;
    const int trow = tid >> 3;
    // gemm-role mapping (verified R8/R11 fragment indices)
    const int gw = wid - 4;
    const int wm = gw & 1;
    const int wn = gw >> 1;
    const int lr = lane >> 2;
    const int lw = lane & 3;

    __half2 mx[4][4];
    const __half2 ninf = __halves2half2(__ushort_as_half(0xFC00),
                                        __ushort_as_half(0xFC00));
#pragma unroll
    for (int i = 0; i < 4; i++)
#pragma unroll
        for (int j = 0; j < 4; j++) mx[i][j] = ninf;
    float acc[2][2][4];
#pragma unroll
    for (int mt = 0; mt < 2; mt++)
#pragma unroll
        for (int nt = 0; nt < 2; nt++)
#pragma unroll
            for (int e = 0; e < 4; e++) acc[mt][nt][e] = 0.0f;

    const int NCH = K / 32;

    // prologue: chunk 0 -> buffer 0
    {
        const unsigned xoff = (unsigned)(xrow * 36 + xq) * 4;
        const unsigned woff = (unsigned)(XTILE_F + wrow * 36 + wq) * 4;
        cp16(sb + xoff,      xg);
        cp16(sb + xoff + 64, xg + 16);
        cp16(sb + woff,      wg);
        asm volatile("cp.async.commit_group;\n");
    }

    for (int c = 0; c < NCH; ++c) {
        const int buf = c & 1;
        if (c + 1 < NCH) {
            const int k0 = (c + 1) * 32;
            const unsigned bb = (unsigned)((buf ^ 1) * BUF_F) * 4u;
            const unsigned xoff = bb + (unsigned)(xrow * 36 + xq) * 4;
            const unsigned woff = bb + (unsigned)(XTILE_F + wrow * 36 + wq) * 4;
            cp16(xoff + sb,      xg + k0);
            cp16(xoff + sb + 64, xg + k0 + 16);
            cp16(woff + sb,      wg + k0);
            asm volatile("cp.async.commit_group;\n");
            asm volatile("cp.async.wait_group 1;\n");
        } else {
            asm volatile("cp.async.wait_group 0;\n");
        }
        __syncthreads();   // B1: buf c staged; previous compute done

        if (wid < 4) {
            // -------- convert fp32 tiles -> fp16 tiles (128 threads) --------
            const float* XF = smf[buf];
            const float* WF = smf[buf] + XTILE_F;
            __half2* X16 = (__half2*)x16s;   // [64][20]
            __half2* W16 = (__half2*)w16s;   // [32][20]
#pragma unroll
            for (int q = 0; q < 8; ++q) {    // X: 1024 half2 pairs
                const int p = q * 128 + tid;
                const int r = p >> 4, kp = p & 15;
                float2 v = *(const float2*)&XF[r * 36 + kp * 2];
                X16[r * 20 + kp] = __floats2half2_rn(v.x, v.y);
            }
#pragma unroll
            for (int q = 0; q < 4; ++q) {    // W: 512 half2 pairs
                const int p = q * 128 + tid;
                const int r = p >> 4, kp = p & 15;
                float2 v = *(const float2*)&WF[r * 36 + kp * 2];
                W16[r * 20 + kp] = __floats2half2_rn(v.x, v.y);
            }
            asm volatile("bar.sync 1, 128;" ::: "memory");

            // -------- MAX term: packed fp16 (HMUL2 + HMAX2) ----------------
#pragma unroll
            for (int kk = 0; kk < 32; kk += 8) {
                uint4 xv[4], wv[4];
#pragma unroll
                for (int i = 0; i < 4; i++)
                    xv[i] = *(const uint4*)&x16s[(trow * 4 + i) * 40 + kk];
#pragma unroll
                for (int j = 0; j < 4; j++)
                    wv[j] = *(const uint4*)&w16s[(tcol + 8 * j) * 40 + kk];
#pragma unroll
                for (int i = 0; i < 4; i++)
#pragma unroll
                    for (int j = 0; j < 4; j++) {
                        const __half2* xh = (const __half2*)&xv[i];
                        const __half2* wh = (const __half2*)&wv[j];
#pragma unroll
                        for (int e = 0; e < 4; e++)
                            mx[i][j] = __hmax2(mx[i][j], __hmul2(xh[e], wh[e]));
                    }
            }
        } else {
            // -------- GEMM warps: in-register tf32 split + 3-pass mma -------
            const float* XF = smf[buf];
            const float* WF = smf[buf] + XTILE_F;
#pragma unroll
            for (int kc = 0; kc < 32; kc += 8) {
                uint32_t ah[2][4], al[2][4];
#pragma unroll
                for (int mt = 0; mt < 2; mt++) {
                    const int base = (wm * 32 + mt * 16 + lr) * 36 + kc + lw;
                    split_tf32(XF[base],              ah[mt][0], al[mt][0]);
                    split_tf32(XF[base + 8 * 36],     ah[mt][1], al[mt][1]);
                    split_tf32(XF[base + 4],          ah[mt][2], al[mt][2]);
                    split_tf32(XF[base + 8 * 36 + 4], ah[mt][3], al[mt][3]);
                }
#pragma unroll
                for (int nt = 0; nt < 2; nt++) {
                    const int base = (wn * 16 + nt * 8 + lr) * 36 + kc + lw;
                    uint32_t bh[2], bl[2];
                    split_tf32(WF[base],     bh[0], bl[0]);
                    split_tf32(WF[base + 4], bh[1], bl[1]);
#pragma unroll
                    for (int mt = 0; mt < 2; mt++) {
                        mma_tf32(acc[mt][nt], ah[mt], bh);
                        mma_tf32(acc[mt][nt], ah[mt], bl);
                        mma_tf32(acc[mt][nt], al[mt], bh);
                    }
                }
            }
        }
        __syncthreads();   // B2: compute(c) done
    }

    // ---- epilogue: max warps publish mx, gemm warps combine + store -------
    float* mxs = smf[0];   // [64][36]; buffer 0 free (last chunk uses buf 1)
    if (wid < 4) {
#pragma unroll
        for (int i = 0; i < 4; i++)
#pragma unroll
            for (int j = 0; j < 4; j++) {
                float m = fmaxf(__low2float(mx[i][j]), __high2float(mx[i][j]));
                mxs[(trow * 4 + i) * 36 + tcol + 8 * j] = BETA * m;
            }
    }
    __syncthreads();

    if (wid >= 4) {
#pragma unroll
        for (int mt = 0; mt < 2; mt++) {
            const int r0 = wm * 32 + mt * 16 + lr;
#pragma unroll
            for (int nt = 0; nt < 2; nt++) {
                const int cc = wn * 16 + nt * 8 + lw * 2;
                const float2 bia = *(const float2*)&bias[n0 + cc];

                float a0 = 0.8f * acc[mt][nt][0] + bia.x + mxs[r0 * 36 + cc];
                float a1 = 0.8f * acc[mt][nt][1] + bia.y + mxs[r0 * 36 + cc + 1];
                float a2 = 0.8f * acc[mt][nt][2] + bia.x + mxs[(r0 + 8) * 36 + cc];
                float a3 = 0.8f * acc[mt][nt][3] + bia.y + mxs[(r0 + 8) * 36 + cc + 1];

                const size_t o0 = (size_t)(m0 + r0) * O + n0 + cc;
                const size_t o1 = (size_t)(m0 + r0 + 8) * O + n0 + cc;
                *(float2*)&act[o0] = make_float2(a0, a1);
                *(float2*)&act[o1] = make_float2(a2, a3);
            }
        }
    }
}

// ---------------- final layer ----------------------------------------------
__global__ void __launch_bounds__(256)
layer4_kernel(const float* __restrict__ X, const float* __restrict__ W,
              const float* __restrict__ bias, float* __restrict__ out, int B)
{
    const int row = blockIdx.x * 8 + (threadIdx.x >> 5);
    const int lane = threadIdx.x & 31;
    if (row >= B) return;

    const float4* xr = (const float4*)(X + (size_t)row * 512);
    const float4* wr = (const float4*)W;

    float acc = 0.0f;
    float mx = -CUDART_INF_F;
#pragma unroll
    for (int it = 0; it < 4; ++it) {
        float4 x = xr[lane + 32 * it];
        float4 w = wr[lane + 32 * it];
        float p0 = x.x * w.x, p1 = x.y * w.y, p2 = x.z * w.z, p3 = x.w * w.w;
        acc += (p0 + p1) + (p2 + p3);
        mx = fmaxf(fmaxf(mx, fmaxf(p0, p1)), fmaxf(p2, p3));
    }
#pragma unroll
    for (int o = 16; o > 0; o >>= 1) {
        acc += __shfl_xor_sync(0xffffffff, acc, o);
        mx = fmaxf(mx, __shfl_xor_sync(0xffffffff, mx, o));
    }
    if (lane == 0)
        out[row] = (1.0f - BETA) * acc + BETA * mx + bias[0];
}

// ---------------- launch ----------------------------------------------------
extern "C" void kernel_launch(void* const* d_in, const int* in_sizes, int n_in,
                              void* d_out, int out_size)
{
    const float* x  = (const float*)d_in[0];
    const float* W1 = (const float*)d_in[1];
    const float* b1 = (const float*)d_in[2];
    const float* W2 = (const float*)d_in[3];
    const float* b2 = (const float*)d_in[4];
    const float* W3 = (const float*)d_in[5];
    const float* b3 = (const float*)d_in[6];
    const float* W4 = (const float*)d_in[7];
    const float* b4 = (const float*)d_in[8];
    float* out = (float*)d_out;

    const int WID = in_sizes[2];        // 512
    const int IN  = in_sizes[1] / WID;  // 256
    const int B   = in_sizes[0] / IN;   // 1024

    float *actA, *actB;
    cudaGetSymbolAddress((void**)&actA, g_actA);
    cudaGetSymbolAddress((void**)&actB, g_actB);

    const dim3 blk(256);
    const dim3 grid(256);   // 16 m-tiles x 16 n-tiles of 64x32

    layer_fused<256><<<grid, blk>>>(x,    W1, b1, actA, WID);
    layer_fused<512><<<grid, blk>>>(actA, W2, b2, actB, WID);
    layer_fused<512><<<grid, blk>>>(actB, W3, b3, actA, WID);
    layer4_kernel<<<B / 8, blk>>>(actA, W4, b4, out, B);
}